// round 1
// baseline (speedup 1.0000x reference)
#include <cuda_runtime.h>
#include <cuda_bf16.h>
#include <math.h>

// Problem constants
#define VOCAB 32000
#define DMODEL 64
#define NLAYERS 4
#define BB 512
#define SS 1000
#define EPS 1e-5f

// Scratch (device globals: allocation-free rule)
__device__ float g_x[BB * SS * DMODEL];        // 131 MB activation buffer (in-place per layer)
__device__ float g_pe[SS * DMODEL];            // positional encoding table
__device__ float g_sums[NLAYERS * BB * DMODEL];// per-batch channel sums feeding each layer's avg
__device__ float g_attn[BB * DMODEL];          // per-batch attn vector for current layer

// ---------------------------------------------------------------------------
// init: zero sums, build PE table
// ---------------------------------------------------------------------------
__global__ void k_init() {
    int i = blockIdx.x * blockDim.x + threadIdx.x;
    int n = blockDim.x * gridDim.x;
    for (int idx = i; idx < NLAYERS * BB * DMODEL; idx += n) g_sums[idx] = 0.0f;
    const float c = -0.14391156634610842f;  // -ln(10000)/64
    for (int idx = i; idx < SS * DMODEL; idx += n) {
        int s = idx >> 6;
        int j = idx & 63;
        float div = expf(c * (float)(j & ~1));
        float ang = (float)s * div;
        g_pe[idx] = (j & 1) ? cosf(ang) : sinf(ang);
    }
}

// ---------------------------------------------------------------------------
// embed: x = emb[tok]*8 + pe[s]; accumulate sums[0]
// grid (8, 512), 256 threads (8 warps). Each block: 128 rows of one batch.
// ---------------------------------------------------------------------------
__global__ __launch_bounds__(256) void k_embed(const int* __restrict__ toks,
                                               const float* __restrict__ emb) {
    int b = blockIdx.y;
    int s0 = blockIdx.x * 128;
    int w = threadIdx.x >> 5, lane = threadIdx.x & 31;
    float acc0 = 0.f, acc1 = 0.f;
    for (int r = w; r < 128; r += 8) {
        int s = s0 + r;
        if (s >= SS) break;
        int tok = toks[b * SS + s];
        float v0 = emb[tok * DMODEL + lane] * 8.0f + g_pe[s * DMODEL + lane];
        float v1 = emb[tok * DMODEL + 32 + lane] * 8.0f + g_pe[s * DMODEL + 32 + lane];
        int row = b * SS + s;
        g_x[row * DMODEL + lane] = v0;
        g_x[row * DMODEL + 32 + lane] = v1;
        acc0 += v0;
        acc1 += v1;
    }
    atomicAdd(&g_sums[0 * BB * DMODEL + b * DMODEL + lane], acc0);
    atomicAdd(&g_sums[0 * BB * DMODEL + b * DMODEL + 32 + lane], acc1);
}

// ---------------------------------------------------------------------------
// attn precompute: attn[b] = (sums[l][b]/S) @ lin_w[l]^T + lin_b[l]
// grid 512, 64 threads
// ---------------------------------------------------------------------------
__global__ void k_attn(const float* __restrict__ lin_w,
                       const float* __restrict__ lin_b, int l) {
    __shared__ float avg[DMODEL];
    int b = blockIdx.x, o = threadIdx.x;
    avg[o] = g_sums[l * BB * DMODEL + b * DMODEL + o] * (1.0f / (float)SS);
    __syncthreads();
    const float* W = lin_w + l * DMODEL * DMODEL + o * DMODEL;
    float a = lin_b[l * DMODEL + o];
#pragma unroll
    for (int k = 0; k < DMODEL; k++) a = fmaf(avg[k], W[k], a);
    g_attn[b * DMODEL + o] = a;
}

// ---------------------------------------------------------------------------
// fused layer kernel: 64-row tile per CTA, one batch per blockIdx.y
//   LN1(x+attn) -> GEMM1+bias+relu -> GEMM2+bias+residual -> LN2
//   l<3: write x, accumulate sums[l+1]; l==3: fused logits head
// smem layout (floats):
//   W1t 0..4351 | W2t 4352.. | yT 8704.. | hT/T 13056..
//   then attn/b1f/b2f/g1/n1/g2/n2/ssum (8*64) | out_w (128) | out_b (2)
// padded stride 68 (16B-aligned rows, conflict-light)
// ---------------------------------------------------------------------------
#define PAD 68
#define SMEM_FLOATS (4 * 64 * PAD + 8 * 64 + 128 + 4)
#define SMEM_BYTES (SMEM_FLOATS * 4)

__global__ __launch_bounds__(256, 3) void k_layer(
    const float* __restrict__ ff1_w, const float* __restrict__ ff1_b,
    const float* __restrict__ ff2_w, const float* __restrict__ ff2_b,
    const float* __restrict__ n1_g, const float* __restrict__ n1_b,
    const float* __restrict__ n2_g, const float* __restrict__ n2_b,
    const float* __restrict__ out_w, const float* __restrict__ out_b,
    float* __restrict__ out, int l) {
    extern __shared__ float smem[];
    float* W1t = smem;
    float* W2t = smem + 64 * PAD;
    float* yT  = smem + 2 * 64 * PAD;
    float* hT  = smem + 3 * 64 * PAD;
    float* sA  = smem + 4 * 64 * PAD;
    float* sB1 = sA + 64;
    float* sB2 = sA + 128;
    float* sG1 = sA + 192;
    float* sN1 = sA + 256;
    float* sG2 = sA + 320;
    float* sN2 = sA + 384;
    float* sSum = sA + 448;
    float* sOW = sA + 512;
    float* sOB = sA + 640;

    int b = blockIdx.y;
    int s0 = blockIdx.x * 64;
    int tid = threadIdx.x;

    // Phase 1: load transposed weights + per-channel params
    const float* W1 = ff1_w + l * 4096;
    const float* W2 = ff2_w + l * 4096;
    for (int i = tid; i < 4096; i += 256) {
        int o = i >> 6, k = i & 63;
        W1t[k * PAD + o] = W1[i];
        W2t[k * PAD + o] = W2[i];
    }
    if (tid < 64) {
        sA[tid]  = g_attn[b * DMODEL + tid];
        sB1[tid] = ff1_b[l * DMODEL + tid];
        sB2[tid] = ff2_b[l * DMODEL + tid];
        sG1[tid] = n1_g[l * DMODEL + tid];
        sN1[tid] = n1_b[l * DMODEL + tid];
        sG2[tid] = n2_g[l * DMODEL + tid];
        sN2[tid] = n2_b[l * DMODEL + tid];
        sSum[tid] = 0.0f;
    }
    if (tid < 128) sOW[tid] = out_w[tid];
    if (tid < 2) sOB[tid] = out_b[tid];
    __syncthreads();

    // Phase 2: load row, add attn, LN1, store transposed yT
    int row = tid >> 2;   // 0..63
    int q = tid & 3;      // channel quarter
    int s = s0 + row;
    bool valid = (s < SS);
    int gbase = (b * SS + s) * DMODEL + q * 16;
    float v[16];
    if (valid) {
#pragma unroll
        for (int i = 0; i < 16; i += 4) {
            float4 t4 = *(const float4*)(g_x + gbase + i);
            v[i] = t4.x; v[i + 1] = t4.y; v[i + 2] = t4.z; v[i + 3] = t4.w;
        }
#pragma unroll
        for (int i = 0; i < 16; i++) v[i] += sA[q * 16 + i];
    } else {
#pragma unroll
        for (int i = 0; i < 16; i++) v[i] = 0.0f;
    }
    float sm = 0.f, sq = 0.f;
#pragma unroll
    for (int i = 0; i < 16; i++) { sm += v[i]; sq += v[i] * v[i]; }
    sm += __shfl_xor_sync(0xffffffffu, sm, 1);
    sq += __shfl_xor_sync(0xffffffffu, sq, 1);
    sm += __shfl_xor_sync(0xffffffffu, sm, 2);
    sq += __shfl_xor_sync(0xffffffffu, sq, 2);
    float mu = sm * (1.0f / 64.0f);
    float var = sq * (1.0f / 64.0f) - mu * mu;
    float rs = rsqrtf(var + EPS);
#pragma unroll
    for (int i = 0; i < 16; i++) {
        int ch = q * 16 + i;
        yT[ch * PAD + row] = (v[i] - mu) * rs * sG1[ch] + sN1[ch];
    }
    __syncthreads();

    // Phase 3: GEMM1 (+bias, relu) -> hT
    int tx = tid & 15, ty = tid >> 4;
    {
        float acc[4][4] = {};
#pragma unroll 8
        for (int k = 0; k < 64; k++) {
            float4 a4 = *(const float4*)(yT + k * PAD + ty * 4);
            float4 w4 = *(const float4*)(W1t + k * PAD + tx * 4);
            float av[4] = {a4.x, a4.y, a4.z, a4.w};
            float wv[4] = {w4.x, w4.y, w4.z, w4.w};
#pragma unroll
            for (int i = 0; i < 4; i++)
#pragma unroll
                for (int j = 0; j < 4; j++) acc[i][j] = fmaf(av[i], wv[j], acc[i][j]);
        }
#pragma unroll
        for (int j = 0; j < 4; j++) {
            int o = tx * 4 + j;
            float bb = sB1[o];
#pragma unroll
            for (int i = 0; i < 4; i++) {
                float h = acc[i][j] + bb;
                hT[o * PAD + ty * 4 + i] = fmaxf(h, 0.0f);
            }
        }
    }
    __syncthreads();

    // Phase 4: GEMM2 + bias + residual
    float tacc[4][4];
    {
        float acc[4][4] = {};
#pragma unroll 8
        for (int k = 0; k < 64; k++) {
            float4 a4 = *(const float4*)(hT + k * PAD + ty * 4);
            float4 w4 = *(const float4*)(W2t + k * PAD + tx * 4);
            float av[4] = {a4.x, a4.y, a4.z, a4.w};
            float wv[4] = {w4.x, w4.y, w4.z, w4.w};
#pragma unroll
            for (int i = 0; i < 4; i++)
#pragma unroll
                for (int j = 0; j < 4; j++) acc[i][j] = fmaf(av[i], wv[j], acc[i][j]);
        }
#pragma unroll
        for (int j = 0; j < 4; j++) {
            int o = tx * 4 + j;
            float bb = sB2[o];
#pragma unroll
            for (int i = 0; i < 4; i++)
                tacc[i][j] = acc[i][j] + bb + yT[o * PAD + ty * 4 + i];
        }
    }
    __syncthreads();  // all hT reads done; reuse hT as row-major T
#pragma unroll
    for (int i = 0; i < 4; i++) {
        float4 t4 = make_float4(tacc[i][0], tacc[i][1], tacc[i][2], tacc[i][3]);
        *(float4*)(hT + (ty * 4 + i) * PAD + tx * 4) = t4;
    }
    __syncthreads();

    // Phase 5: LN2 + epilogue
#pragma unroll
    for (int i = 0; i < 16; i += 4) {
        float4 t4 = *(const float4*)(hT + row * PAD + q * 16 + i);
        v[i] = t4.x; v[i + 1] = t4.y; v[i + 2] = t4.z; v[i + 3] = t4.w;
    }
    sm = 0.f; sq = 0.f;
#pragma unroll
    for (int i = 0; i < 16; i++) { sm += v[i]; sq += v[i] * v[i]; }
    sm += __shfl_xor_sync(0xffffffffu, sm, 1);
    sq += __shfl_xor_sync(0xffffffffu, sq, 1);
    sm += __shfl_xor_sync(0xffffffffu, sm, 2);
    sq += __shfl_xor_sync(0xffffffffu, sq, 2);
    mu = sm * (1.0f / 64.0f);
    var = sq * (1.0f / 64.0f) - mu * mu;
    rs = rsqrtf(var + EPS);
    float nrm[16];
#pragma unroll
    for (int i = 0; i < 16; i++) {
        int ch = q * 16 + i;
        nrm[i] = (v[i] - mu) * rs * sG2[ch] + sN2[ch];
    }

    if (l < NLAYERS - 1) {
        if (valid) {
#pragma unroll
            for (int i = 0; i < 16; i += 4)
                *(float4*)(g_x + gbase + i) =
                    make_float4(nrm[i], nrm[i + 1], nrm[i + 2], nrm[i + 3]);
#pragma unroll
            for (int i = 0; i < 16; i++) atomicAdd(&sSum[q * 16 + i], nrm[i]);
        }
        __syncthreads();
        if (tid < 64)
            atomicAdd(&g_sums[(l + 1) * BB * DMODEL + b * DMODEL + tid], sSum[tid]);
    } else {
        float p0 = 0.f, p1 = 0.f;
#pragma unroll
        for (int i = 0; i < 16; i++) {
            int ch = q * 16 + i;
            p0 = fmaf(nrm[i], sOW[ch], p0);
            p1 = fmaf(nrm[i], sOW[64 + ch], p1);
        }
        p0 += __shfl_xor_sync(0xffffffffu, p0, 1);
        p1 += __shfl_xor_sync(0xffffffffu, p1, 1);
        p0 += __shfl_xor_sync(0xffffffffu, p0, 2);
        p1 += __shfl_xor_sync(0xffffffffu, p1, 2);
        if (valid && q == 0) {
            out[(b * SS + s) * 2 + 0] = p0 + sOB[0];
            out[(b * SS + s) * 2 + 1] = p1 + sOB[1];
        }
    }
}

// ---------------------------------------------------------------------------
extern "C" void kernel_launch(void* const* d_in, const int* in_sizes, int n_in,
                              void* d_out, int out_size) {
    const int*   tokens = (const int*)d_in[0];
    const float* emb    = (const float*)d_in[1];
    const float* lin_w  = (const float*)d_in[2];
    const float* lin_b  = (const float*)d_in[3];
    const float* ff1_w  = (const float*)d_in[4];
    const float* ff1_b  = (const float*)d_in[5];
    const float* ff2_w  = (const float*)d_in[6];
    const float* ff2_b  = (const float*)d_in[7];
    const float* n1g    = (const float*)d_in[8];
    const float* n1b    = (const float*)d_in[9];
    const float* n2g    = (const float*)d_in[10];
    const float* n2b    = (const float*)d_in[11];
    const float* ow     = (const float*)d_in[12];
    const float* ob     = (const float*)d_in[13];
    float* out = (float*)d_out;

    cudaFuncSetAttribute(k_layer, cudaFuncAttributeMaxDynamicSharedMemorySize,
                         SMEM_BYTES);

    k_init<<<128, 256>>>();
    k_embed<<<dim3(8, BB), 256>>>(tokens, emb);
    for (int l = 0; l < NLAYERS; l++) {
        k_attn<<<BB, 64>>>(lin_w, lin_b, l);
        k_layer<<<dim3(16, BB), 256, SMEM_BYTES>>>(ff1_w, ff1_b, ff2_w, ff2_b,
                                                   n1g, n1b, n2g, n2b, ow, ob,
                                                   out, l);
    }
}

// round 5
// speedup vs baseline: 2.5665x; 2.5665x over previous
#include <cuda_runtime.h>
#include <cuda_bf16.h>
#include <math.h>
#include <stdint.h>

#define VOCAB 32000
#define DMODEL 64
#define NLAYERS 4
#define BB 512
#define SS 1000
#define EPS 1e-5f

// Scratch (device globals: allocation-free rule)
__device__ float g_x[BB * SS * DMODEL];
__device__ float g_pe[SS * DMODEL];
__device__ float g_sums[NLAYERS * BB * DMODEL];
__device__ float g_attn[BB * DMODEL];

// ---------------------------------------------------------------------------
// warp-MMA helpers (sm_80+ instructions; safe for plain sm_103 target)
// ---------------------------------------------------------------------------
__device__ __forceinline__ uint32_t smem_u32(const void* p) {
    uint32_t a;
    asm("{ .reg .u64 t; cvta.to.shared.u64 t, %1; cvt.u32.u64 %0, t; }"
        : "=r"(a) : "l"(p));
    return a;
}

#define LDSM4(r0, r1, r2, r3, addr)                                         \
    asm volatile("ldmatrix.sync.aligned.m8n8.x4.shared.b16 {%0,%1,%2,%3}, [%4];" \
                 : "=r"(r0), "=r"(r1), "=r"(r2), "=r"(r3) : "r"(addr))

#define MMA_BF16(d0, d1, d2, d3, a0, a1, a2, a3, b0, b1)                    \
    asm volatile("mma.sync.aligned.m16n8k16.row.col.f32.bf16.bf16.f32 "     \
                 "{%0,%1,%2,%3}, {%4,%5,%6,%7}, {%8,%9}, {%0,%1,%2,%3};"    \
                 : "+f"(d0), "+f"(d1), "+f"(d2), "+f"(d3)                   \
                 : "r"(a0), "r"(a1), "r"(a2), "r"(a3), "r"(b0), "r"(b1))

// strides (bytes)
#define A_STRIDE 144   // 72 bf16 per row (pad 8) -> conflict-free ldmatrix
#define W_STRIDE 144
#define ST_STRIDE 68   // floats

// one K=64 pass: D += A(16x64, frags in a[16]) * W(64x64 at wb)^T
__device__ __forceinline__ void gemm_pass(float (&d)[8][4], const uint32_t* a,
                                          uint32_t wb, int lane) {
    uint32_t bg = lane >> 3;
    uint32_t brow = ((bg & 2u) << 2) | (lane & 7u);
    uint32_t bko = (bg & 1u) << 4;
#pragma unroll
    for (int kt = 0; kt < 4; kt++) {
#pragma unroll
        for (int ntp = 0; ntp < 4; ntp++) {
            uint32_t addr = wb + (ntp * 16 + brow) * W_STRIDE + kt * 32 + bko;
            uint32_t b0, b1, b2, b3;
            LDSM4(b0, b1, b2, b3, addr);
            MMA_BF16(d[2 * ntp][0], d[2 * ntp][1], d[2 * ntp][2], d[2 * ntp][3],
                     a[4 * kt], a[4 * kt + 1], a[4 * kt + 2], a[4 * kt + 3],
                     b0, b1);
            MMA_BF16(d[2 * ntp + 1][0], d[2 * ntp + 1][1], d[2 * ntp + 1][2],
                     d[2 * ntp + 1][3],
                     a[4 * kt], a[4 * kt + 1], a[4 * kt + 2], a[4 * kt + 3],
                     b2, b3);
        }
    }
}

__device__ __forceinline__ void load_afrags(uint32_t (&a)[16], uint32_t ab,
                                            int wi, int lane) {
    uint32_t row = wi * 16 + (lane & 15);
    uint32_t ko = (uint32_t)(lane >> 4) << 4;
#pragma unroll
    for (int kt = 0; kt < 4; kt++) {
        uint32_t addr = ab + row * A_STRIDE + kt * 32 + ko;
        LDSM4(a[4 * kt], a[4 * kt + 1], a[4 * kt + 2], a[4 * kt + 3], addr);
    }
}

__device__ __forceinline__ uint32_t pack_hi(float f0, float f1) {
    __nv_bfloat16 h0 = __float2bfloat16_rn(f0);
    __nv_bfloat16 h1 = __float2bfloat16_rn(f1);
    return ((uint32_t)__bfloat16_as_ushort(h1) << 16) | __bfloat16_as_ushort(h0);
}
__device__ __forceinline__ uint32_t pack_lo(float f0, float f1, uint32_t hi) {
    __nv_bfloat16 h0 = __ushort_as_bfloat16((unsigned short)(hi & 0xFFFF));
    __nv_bfloat16 h1 = __ushort_as_bfloat16((unsigned short)(hi >> 16));
    __nv_bfloat16 q0 = __float2bfloat16_rn(f0 - __bfloat162float(h0));
    __nv_bfloat16 q1 = __float2bfloat16_rn(f1 - __bfloat162float(h1));
    return ((uint32_t)__bfloat16_as_ushort(q1) << 16) | __bfloat16_as_ushort(q0);
}

// ---------------------------------------------------------------------------
// init / embed / attn
// ---------------------------------------------------------------------------
__global__ void k_init() {
    int i = blockIdx.x * blockDim.x + threadIdx.x;
    int n = blockDim.x * gridDim.x;
    for (int idx = i; idx < NLAYERS * BB * DMODEL; idx += n) g_sums[idx] = 0.0f;
    const float c = -0.14391156634610842f;
    for (int idx = i; idx < SS * DMODEL; idx += n) {
        int s = idx >> 6;
        int j = idx & 63;
        float div = expf(c * (float)(j & ~1));
        float ang = (float)s * div;
        g_pe[idx] = (j & 1) ? cosf(ang) : sinf(ang);
    }
}

__global__ __launch_bounds__(256) void k_embed(const int* __restrict__ toks,
                                               const float* __restrict__ emb) {
    int b = blockIdx.y;
    int s0 = blockIdx.x * 128;
    int w = threadIdx.x >> 5, lane = threadIdx.x & 31;
    float acc0 = 0.f, acc1 = 0.f;
    for (int r = w; r < 128; r += 8) {
        int s = s0 + r;
        if (s >= SS) break;
        int tok = toks[b * SS + s];
        float v0 = emb[tok * DMODEL + lane] * 8.0f + g_pe[s * DMODEL + lane];
        float v1 = emb[tok * DMODEL + 32 + lane] * 8.0f + g_pe[s * DMODEL + 32 + lane];
        int row = b * SS + s;
        g_x[row * DMODEL + lane] = v0;
        g_x[row * DMODEL + 32 + lane] = v1;
        acc0 += v0;
        acc1 += v1;
    }
    atomicAdd(&g_sums[0 * BB * DMODEL + b * DMODEL + lane], acc0);
    atomicAdd(&g_sums[0 * BB * DMODEL + b * DMODEL + 32 + lane], acc1);
}

__global__ void k_attn(const float* __restrict__ lin_w,
                       const float* __restrict__ lin_b, int l) {
    __shared__ float avg[DMODEL];
    int b = blockIdx.x, o = threadIdx.x;
    avg[o] = g_sums[l * BB * DMODEL + b * DMODEL + o] * (1.0f / (float)SS);
    __syncthreads();
    const float* W = lin_w + l * DMODEL * DMODEL + o * DMODEL;
    float a = lin_b[l * DMODEL + o];
#pragma unroll
    for (int k = 0; k < DMODEL; k++) a = fmaf(avg[k], W[k], a);
    g_attn[b * DMODEL + o] = a;
}

// ---------------------------------------------------------------------------
// fused layer kernel: 128 rows/CTA, 8 warps, warp-local mainloop with HMMA.
// smem: params | stage f32(128x68) | Ah | Al | W1h | W1l | W2h | W2l
// ---------------------------------------------------------------------------
#define SM_P 0
#define SM_STAGE 2816
#define SM_AH (SM_STAGE + 34816)
#define SM_AL (SM_AH + 18432)
#define SM_W1H (SM_AL + 18432)
#define SM_W1L (SM_W1H + 9216)
#define SM_W2H (SM_W1L + 9216)
#define SM_W2L (SM_W2H + 9216)
#define SM_TOTAL (SM_W2L + 9216)

#define P_ATTN 0
#define P_B1 64
#define P_B2 128
#define P_G1 192
#define P_N1 256
#define P_G2 320
#define P_N2 384
#define P_OW 448
#define P_OB 576

__global__ __launch_bounds__(256, 2)
void k_layer3(const float* __restrict__ ff1_w, const float* __restrict__ ff1_b,
              const float* __restrict__ ff2_w, const float* __restrict__ ff2_b,
              const float* __restrict__ n1_g, const float* __restrict__ n1_b,
              const float* __restrict__ n2_g, const float* __restrict__ n2_b,
              const float* __restrict__ out_w, const float* __restrict__ out_b,
              float* __restrict__ out, int l) {
    extern __shared__ char sm[];
    float* P = (float*)(sm + SM_P);
    float* stage = (float*)(sm + SM_STAGE);
    uint32_t smb = smem_u32(sm);

    int tid = threadIdx.x;
    int wi = tid >> 5;
    int lane = tid & 31;
    int b = blockIdx.y;
    int s0 = blockIdx.x * 128;
    int rows_valid = SS - s0;
    if (rows_valid > 128) rows_valid = 128;

    // Phase 0: params + split-bf16 weight tiles
    if (tid < 64) {
        P[P_ATTN + tid] = g_attn[b * DMODEL + tid];
        P[P_B1 + tid] = ff1_b[l * DMODEL + tid];
        P[P_B2 + tid] = ff2_b[l * DMODEL + tid];
        P[P_G1 + tid] = n1_g[l * DMODEL + tid];
        P[P_N1 + tid] = n1_b[l * DMODEL + tid];
        P[P_G2 + tid] = n2_g[l * DMODEL + tid];
        P[P_N2 + tid] = n2_b[l * DMODEL + tid];
    }
    if (tid < 128) P[P_OW + tid] = out_w[tid];
    if (tid < 2) P[P_OB + tid] = out_b[tid];

    const float* W1 = ff1_w + l * 4096;
    const float* W2 = ff2_w + l * 4096;
    for (int i = tid; i < 2048; i += 256) {
        int o = i >> 5, k2 = i & 31;
        int boff = o * W_STRIDE + k2 * 4;
        {
            float w0 = W1[o * 64 + k2 * 2], w1 = W1[o * 64 + k2 * 2 + 1];
            uint32_t hi = pack_hi(w0, w1);
            *(uint32_t*)(sm + SM_W1H + boff) = hi;
            *(uint32_t*)(sm + SM_W1L + boff) = pack_lo(w0, w1, hi);
        }
        {
            float w0 = W2[o * 64 + k2 * 2], w1 = W2[o * 64 + k2 * 2 + 1];
            uint32_t hi = pack_hi(w0, w1);
            *(uint32_t*)(sm + SM_W2H + boff) = hi;
            *(uint32_t*)(sm + SM_W2L + boff) = pack_lo(w0, w1, hi);
        }
    }

    // Phase 1: x tile -> fp32 stage
    for (int i = tid; i < 2048; i += 256) {
        int row = i >> 4, c4 = i & 15;
        float4 t;
        if (row < rows_valid)
            t = *(const float4*)(g_x + (b * SS + s0 + row) * 64 + c4 * 4);
        else
            t = make_float4(0.f, 0.f, 0.f, 0.f);
        *(float4*)(stage + row * ST_STRIDE + c4 * 4) = t;
    }
    __syncthreads();

    // Phase 2: LN1 (2 threads/row, 32 cols each); y -> stage(fp32) + Ah/Al
    {
        int row = tid >> 1;
        int half = tid & 1;
        float v[32];
#pragma unroll
        for (int i = 0; i < 32; i += 4) {
            float4 t = *(const float4*)(stage + row * ST_STRIDE + half * 32 + i);
            v[i] = t.x; v[i + 1] = t.y; v[i + 2] = t.z; v[i + 3] = t.w;
        }
        float smu = 0.f, ssq = 0.f;
#pragma unroll
        for (int i = 0; i < 32; i++) {
            v[i] += P[P_ATTN + half * 32 + i];
            smu += v[i];
            ssq += v[i] * v[i];
        }
        smu += __shfl_xor_sync(0xffffffffu, smu, 1);
        ssq += __shfl_xor_sync(0xffffffffu, ssq, 1);
        float mu = smu * (1.0f / 64.0f);
        float var = ssq * (1.0f / 64.0f) - mu * mu;
        float rs = rsqrtf(var + EPS);
#pragma unroll
        for (int i = 0; i < 32; i++) {
            int ch = half * 32 + i;
            v[i] = (v[i] - mu) * rs * P[P_G1 + ch] + P[P_N1 + ch];
        }
        // write y fp32 back (residual) + bf16 splits
#pragma unroll
        for (int i = 0; i < 32; i += 4)
            *(float4*)(stage + row * ST_STRIDE + half * 32 + i) =
                make_float4(v[i], v[i + 1], v[i + 2], v[i + 3]);
#pragma unroll
        for (int i = 0; i < 32; i += 2) {
            int boff = row * A_STRIDE + (half * 32 + i) * 2;
            uint32_t hi = pack_hi(v[i], v[i + 1]);
            *(uint32_t*)(sm + SM_AH + boff) = hi;
            *(uint32_t*)(sm + SM_AL + boff) = pack_lo(v[i], v[i + 1], hi);
        }
    }
    __syncwarp();

    // Phase 3: GEMM1 = y @ W1^T  (3-pass split bf16)
    float d1[8][4];
#pragma unroll
    for (int n = 0; n < 8; n++)
#pragma unroll
        for (int j = 0; j < 4; j++) d1[n][j] = 0.f;
    {
        uint32_t a[16];
        load_afrags(a, smb + SM_AH, wi, lane);
        gemm_pass(d1, a, smb + SM_W1H, lane);
        gemm_pass(d1, a, smb + SM_W1L, lane);
        load_afrags(a, smb + SM_AL, wi, lane);
        gemm_pass(d1, a, smb + SM_W1H, lane);
    }

    // Phase 4: h = relu(d1 + b1) -> Ah/Al (warp-local rows)
    {
        int q = lane >> 2, j = lane & 3;
        int r0 = wi * 16 + q, r1 = r0 + 8;
#pragma unroll
        for (int nt = 0; nt < 8; nt++) {
            int c = nt * 8 + 2 * j;
            float b1a = P[P_B1 + c], b1b = P[P_B1 + c + 1];
            float h0 = fmaxf(d1[nt][0] + b1a, 0.f);
            float h1 = fmaxf(d1[nt][1] + b1b, 0.f);
            float h2 = fmaxf(d1[nt][2] + b1a, 0.f);
            float h3 = fmaxf(d1[nt][3] + b1b, 0.f);
            uint32_t hi0 = pack_hi(h0, h1);
            uint32_t hi1 = pack_hi(h2, h3);
            *(uint32_t*)(sm + SM_AH + r0 * A_STRIDE + c * 2) = hi0;
            *(uint32_t*)(sm + SM_AL + r0 * A_STRIDE + c * 2) = pack_lo(h0, h1, hi0);
            *(uint32_t*)(sm + SM_AH + r1 * A_STRIDE + c * 2) = hi1;
            *(uint32_t*)(sm + SM_AL + r1 * A_STRIDE + c * 2) = pack_lo(h2, h3, hi1);
        }
    }
    __syncwarp();

    // Phase 5: GEMM2 = h @ W2^T
    float d2[8][4];
#pragma unroll
    for (int n = 0; n < 8; n++)
#pragma unroll
        for (int j = 0; j < 4; j++) d2[n][j] = 0.f;
    {
        uint32_t a[16];
        load_afrags(a, smb + SM_AH, wi, lane);
        gemm_pass(d2, a, smb + SM_W2H, lane);
        gemm_pass(d2, a, smb + SM_W2L, lane);
        load_afrags(a, smb + SM_AL, wi, lane);
        gemm_pass(d2, a, smb + SM_W2H, lane);
    }

    // Phase 6: residual + bias + LN2 (frag layout; quad shuffles) -> stage
    {
        int q = lane >> 2, j = lane & 3;
        int r0 = wi * 16 + q, r1 = r0 + 8;
        float v0[16], v1[16];
        float sm0 = 0.f, sq0 = 0.f, sm1 = 0.f, sq1 = 0.f;
#pragma unroll
        for (int nt = 0; nt < 8; nt++) {
            int c = nt * 8 + 2 * j;
            float b2a = P[P_B2 + c], b2b = P[P_B2 + c + 1];
            float2 y0 = *(const float2*)(stage + r0 * ST_STRIDE + c);
            float2 y1 = *(const float2*)(stage + r1 * ST_STRIDE + c);
            float a0 = d2[nt][0] + b2a + y0.x;
            float a1 = d2[nt][1] + b2b + y0.y;
            float a2 = d2[nt][2] + b2a + y1.x;
            float a3 = d2[nt][3] + b2b + y1.y;
            v0[2 * nt] = a0; v0[2 * nt + 1] = a1;
            v1[2 * nt] = a2; v1[2 * nt + 1] = a3;
            sm0 += a0 + a1; sq0 += a0 * a0 + a1 * a1;
            sm1 += a2 + a3; sq1 += a2 * a2 + a3 * a3;
        }
        sm0 += __shfl_xor_sync(0xffffffffu, sm0, 1);
        sq0 += __shfl_xor_sync(0xffffffffu, sq0, 1);
        sm1 += __shfl_xor_sync(0xffffffffu, sm1, 1);
        sq1 += __shfl_xor_sync(0xffffffffu, sq1, 1);
        sm0 += __shfl_xor_sync(0xffffffffu, sm0, 2);
        sq0 += __shfl_xor_sync(0xffffffffu, sq0, 2);
        sm1 += __shfl_xor_sync(0xffffffffu, sm1, 2);
        sq1 += __shfl_xor_sync(0xffffffffu, sq1, 2);
        float mu0 = sm0 * (1.0f / 64.0f);
        float rs0 = rsqrtf(sq0 * (1.0f / 64.0f) - mu0 * mu0 + EPS);
        float mu1 = sm1 * (1.0f / 64.0f);
        float rs1 = rsqrtf(sq1 * (1.0f / 64.0f) - mu1 * mu1 + EPS);
#pragma unroll
        for (int nt = 0; nt < 8; nt++) {
            int c = nt * 8 + 2 * j;
            float g0 = P[P_G2 + c], g1v = P[P_G2 + c + 1];
            float n0 = P[P_N2 + c], n1v = P[P_N2 + c + 1];
            float2 o0 = make_float2((v0[2 * nt] - mu0) * rs0 * g0 + n0,
                                    (v0[2 * nt + 1] - mu0) * rs0 * g1v + n1v);
            float2 o1 = make_float2((v1[2 * nt] - mu1) * rs1 * g0 + n0,
                                    (v1[2 * nt + 1] - mu1) * rs1 * g1v + n1v);
            *(float2*)(stage + r0 * ST_STRIDE + c) = o0;
            *(float2*)(stage + r1 * ST_STRIDE + c) = o1;
        }
    }
    __syncthreads();

    // Phase 7: writeback
    if (l < NLAYERS - 1) {
        for (int i = tid; i < rows_valid * 16; i += 256) {
            int row = i >> 4, c4 = i & 15;
            *(float4*)(g_x + (b * SS + s0 + row) * 64 + c4 * 4) =
                *(const float4*)(stage + row * ST_STRIDE + c4 * 4);
        }
        if (tid < 64) {
            float s = 0.f;
            for (int rr = 0; rr < rows_valid; rr++) s += stage[rr * ST_STRIDE + tid];
            atomicAdd(&g_sums[(l + 1) * BB * DMODEL + b * DMODEL + tid], s);
        }
    } else {
        if (tid < 128 && tid < rows_valid) {
            int row = tid;
            float p0 = P[P_OB + 0], p1 = P[P_OB + 1];
#pragma unroll
            for (int c = 0; c < 64; c++) {
                float yv = stage[row * ST_STRIDE + c];
                p0 = fmaf(yv, P[P_OW + c], p0);
                p1 = fmaf(yv, P[P_OW + 64 + c], p1);
            }
            out[(b * SS + s0 + row) * 2 + 0] = p0;
            out[(b * SS + s0 + row) * 2 + 1] = p1;
        }
    }
}

// ---------------------------------------------------------------------------
extern "C" void kernel_launch(void* const* d_in, const int* in_sizes, int n_in,
                              void* d_out, int out_size) {
    const int*   tokens = (const int*)d_in[0];
    const float* emb    = (const float*)d_in[1];
    const float* lin_w  = (const float*)d_in[2];
    const float* lin_b  = (const float*)d_in[3];
    const float* ff1_w  = (const float*)d_in[4];
    const float* ff1_b  = (const float*)d_in[5];
    const float* ff2_w  = (const float*)d_in[6];
    const float* ff2_b  = (const float*)d_in[7];
    const float* n1g    = (const float*)d_in[8];
    const float* n1b    = (const float*)d_in[9];
    const float* n2g    = (const float*)d_in[10];
    const float* n2b    = (const float*)d_in[11];
    const float* ow     = (const float*)d_in[12];
    const float* ob     = (const float*)d_in[13];
    float* out = (float*)d_out;

    cudaFuncSetAttribute(k_layer3, cudaFuncAttributeMaxDynamicSharedMemorySize,
                         SM_TOTAL);

    k_init<<<128, 256>>>();
    k_embed<<<dim3(8, BB), 256>>>(tokens, emb);
    for (int l = 0; l < NLAYERS; l++) {
        k_attn<<<BB, 64>>>(lin_w, lin_b, l);
        k_layer3<<<dim3(8, BB), 256, SM_TOTAL>>>(ff1_w, ff1_b, ff2_w, ff2_b,
                                                 n1g, n1b, n2g, n2b, ow, ob,
                                                 out, l);
    }
}

// round 6
// speedup vs baseline: 3.5519x; 1.3839x over previous
#include <cuda_runtime.h>
#include <cuda_bf16.h>
#include <math.h>
#include <stdint.h>

#define VOCAB 32000
#define DMODEL 64
#define NLAYERS 4
#define BB 512
#define SS 1000
#define EPS 1e-5f

__device__ float g_x[BB * SS * DMODEL];
__device__ float g_pe[SS * DMODEL];
__device__ float g_sums[NLAYERS * BB * DMODEL];
__device__ float g_attn[BB * DMODEL];

// ---------------------------------------------------------------------------
__device__ __forceinline__ uint32_t smem_u32(const void* p) {
    uint32_t a;
    asm("{ .reg .u64 t; cvta.to.shared.u64 t, %1; cvt.u32.u64 %0, t; }"
        : "=r"(a) : "l"(p));
    return a;
}

#define LDSM4(r0, r1, r2, r3, addr)                                         \
    asm volatile("ldmatrix.sync.aligned.m8n8.x4.shared.b16 {%0,%1,%2,%3}, [%4];" \
                 : "=r"(r0), "=r"(r1), "=r"(r2), "=r"(r3) : "r"(addr))

#define MMA_BF16(d0, d1, d2, d3, a0, a1, a2, a3, b0, b1)                    \
    asm volatile("mma.sync.aligned.m16n8k16.row.col.f32.bf16.bf16.f32 "     \
                 "{%0,%1,%2,%3}, {%4,%5,%6,%7}, {%8,%9}, {%0,%1,%2,%3};"    \
                 : "+f"(d0), "+f"(d1), "+f"(d2), "+f"(d3)                   \
                 : "r"(a0), "r"(a1), "r"(a2), "r"(a3), "r"(b0), "r"(b1))

__device__ __forceinline__ uint32_t pack_hi(float f0, float f1) {
    __nv_bfloat16 h0 = __float2bfloat16_rn(f0);
    __nv_bfloat16 h1 = __float2bfloat16_rn(f1);
    return ((uint32_t)__bfloat16_as_ushort(h1) << 16) | __bfloat16_as_ushort(h0);
}
__device__ __forceinline__ uint32_t pack_lo(float f0, float f1, uint32_t hi) {
    __nv_bfloat16 h0 = __ushort_as_bfloat16((unsigned short)(hi & 0xFFFF));
    __nv_bfloat16 h1 = __ushort_as_bfloat16((unsigned short)(hi >> 16));
    __nv_bfloat16 q0 = __float2bfloat16_rn(f0 - __bfloat162float(h0));
    __nv_bfloat16 q1 = __float2bfloat16_rn(f1 - __bfloat162float(h1));
    return ((uint32_t)__bfloat16_as_ushort(q1) << 16) | __bfloat16_as_ushort(q0);
}
__device__ __forceinline__ float unpack_add(uint32_t hi, uint32_t lo, int half) {
    unsigned short h = half ? (unsigned short)(hi >> 16) : (unsigned short)(hi & 0xFFFF);
    unsigned short l = half ? (unsigned short)(lo >> 16) : (unsigned short)(lo & 0xFFFF);
    return __bfloat162float(__ushort_as_bfloat16(h)) +
           __bfloat162float(__ushort_as_bfloat16(l));
}

// swizzled byte offset inside a 64x128B tile: row r, 16B-chunk c (0..7), +sub
__device__ __forceinline__ uint32_t tile_off(uint32_t r, uint32_t c) {
    return r * 128 + ((c ^ (r & 7u)) << 4);
}

// ---------------------------------------------------------------------------
__global__ void k_init() {
    int i = blockIdx.x * blockDim.x + threadIdx.x;
    int n = blockDim.x * gridDim.x;
    for (int idx = i; idx < NLAYERS * BB * DMODEL; idx += n) g_sums[idx] = 0.0f;
    const float c = -0.14391156634610842f;
    for (int idx = i; idx < SS * DMODEL; idx += n) {
        int s = idx >> 6;
        int j = idx & 63;
        float div = expf(c * (float)(j & ~1));
        float ang = (float)s * div;
        g_pe[idx] = (j & 1) ? cosf(ang) : sinf(ang);
    }
}

__global__ __launch_bounds__(256) void k_embed(const int* __restrict__ toks,
                                               const float* __restrict__ emb) {
    int b = blockIdx.y;
    int s0 = blockIdx.x * 128;
    int w = threadIdx.x >> 5, lane = threadIdx.x & 31;
    float acc0 = 0.f, acc1 = 0.f;
    for (int r = w; r < 128; r += 8) {
        int s = s0 + r;
        if (s >= SS) break;
        int tok = toks[b * SS + s];
        float v0 = emb[tok * DMODEL + lane] * 8.0f + g_pe[s * DMODEL + lane];
        float v1 = emb[tok * DMODEL + 32 + lane] * 8.0f + g_pe[s * DMODEL + 32 + lane];
        int row = b * SS + s;
        g_x[row * DMODEL + lane] = v0;
        g_x[row * DMODEL + 32 + lane] = v1;
        acc0 += v0;
        acc1 += v1;
    }
    atomicAdd(&g_sums[0 * BB * DMODEL + b * DMODEL + lane], acc0);
    atomicAdd(&g_sums[0 * BB * DMODEL + b * DMODEL + 32 + lane], acc1);
}

__global__ void k_attn(const float* __restrict__ lin_w,
                       const float* __restrict__ lin_b, int l) {
    __shared__ float avg[DMODEL];
    int b = blockIdx.x, o = threadIdx.x;
    avg[o] = g_sums[l * BB * DMODEL + b * DMODEL + o] * (1.0f / (float)SS);
    __syncthreads();
    const float* W = lin_w + l * DMODEL * DMODEL + o * DMODEL;
    float a = lin_b[l * DMODEL + o];
#pragma unroll
    for (int k = 0; k < DMODEL; k++) a = fmaf(avg[k], W[k], a);
    g_attn[b * DMODEL + o] = a;
}

// ---------------------------------------------------------------------------
// k_layer4: 64 rows/CTA, 4 warps (16 rows each), 128 threads, 4 CTAs/SM.
// All tiles 64x128B, XOR-swizzled. Relu output overwrites W1 tiles.
// ---------------------------------------------------------------------------
#define P_ATTN 0
#define P_B1 64
#define P_B2 128
#define P_G1 192
#define P_N1 256
#define P_G2 320
#define P_N2 384
#define P_OW 448
#define P_OB 576
#define P_SUM 640

#define SM_AH 2816
#define SM_AL (SM_AH + 8192)
#define SM_W1H (SM_AL + 8192)
#define SM_W1L (SM_W1H + 8192)
#define SM_W2H (SM_W1L + 8192)
#define SM_W2L (SM_W2H + 8192)
#define SM_TOTAL (SM_W2L + 8192)

// one fused GEMM: D = Ah*Wh + Ah*Wl + Al*Wh  (K=64), Wh LDSM shared
__device__ __forceinline__ void gemm64(float (&d)[8][4], uint32_t aHb,
                                       uint32_t aLb, uint32_t wHb, uint32_t wLb,
                                       int wi, int lane) {
    uint32_t aH[16], aL[16];
    uint32_t arow = (uint32_t)(wi * 16) + (lane & 15);
    uint32_t acsub = (uint32_t)(lane >> 4);
#pragma unroll
    for (int kt = 0; kt < 4; kt++) {
        uint32_t off = tile_off(arow, kt * 2 + acsub);
        LDSM4(aH[4 * kt], aH[4 * kt + 1], aH[4 * kt + 2], aH[4 * kt + 3], aHb + off);
        LDSM4(aL[4 * kt], aL[4 * kt + 1], aL[4 * kt + 2], aL[4 * kt + 3], aLb + off);
    }
    uint32_t bg = (uint32_t)(lane >> 3);
    uint32_t wrow_in = ((bg & 2u) << 2) | (lane & 7u);
    uint32_t wcsub = bg & 1u;
#pragma unroll
    for (int ntp = 0; ntp < 4; ntp++) {
#pragma unroll
        for (int kt = 0; kt < 4; kt++) {
            uint32_t wrow = ntp * 16 + wrow_in;
            uint32_t off = tile_off(wrow, kt * 2 + wcsub);
            uint32_t h0, h1, h2, h3;
            LDSM4(h0, h1, h2, h3, wHb + off);
            MMA_BF16(d[2 * ntp][0], d[2 * ntp][1], d[2 * ntp][2], d[2 * ntp][3],
                     aH[4 * kt], aH[4 * kt + 1], aH[4 * kt + 2], aH[4 * kt + 3], h0, h1);
            MMA_BF16(d[2 * ntp + 1][0], d[2 * ntp + 1][1], d[2 * ntp + 1][2], d[2 * ntp + 1][3],
                     aH[4 * kt], aH[4 * kt + 1], aH[4 * kt + 2], aH[4 * kt + 3], h2, h3);
            MMA_BF16(d[2 * ntp][0], d[2 * ntp][1], d[2 * ntp][2], d[2 * ntp][3],
                     aL[4 * kt], aL[4 * kt + 1], aL[4 * kt + 2], aL[4 * kt + 3], h0, h1);
            MMA_BF16(d[2 * ntp + 1][0], d[2 * ntp + 1][1], d[2 * ntp + 1][2], d[2 * ntp + 1][3],
                     aL[4 * kt], aL[4 * kt + 1], aL[4 * kt + 2], aL[4 * kt + 3], h2, h3);
            uint32_t l0, l1, l2, l3;
            LDSM4(l0, l1, l2, l3, wLb + off);
            MMA_BF16(d[2 * ntp][0], d[2 * ntp][1], d[2 * ntp][2], d[2 * ntp][3],
                     aH[4 * kt], aH[4 * kt + 1], aH[4 * kt + 2], aH[4 * kt + 3], l0, l1);
            MMA_BF16(d[2 * ntp + 1][0], d[2 * ntp + 1][1], d[2 * ntp + 1][2], d[2 * ntp + 1][3],
                     aH[4 * kt], aH[4 * kt + 1], aH[4 * kt + 2], aH[4 * kt + 3], l2, l3);
        }
    }
}

__global__ __launch_bounds__(128, 4)
void k_layer4(const float* __restrict__ ff1_w, const float* __restrict__ ff1_b,
              const float* __restrict__ ff2_w, const float* __restrict__ ff2_b,
              const float* __restrict__ n1_g, const float* __restrict__ n1_b,
              const float* __restrict__ n2_g, const float* __restrict__ n2_b,
              const float* __restrict__ out_w, const float* __restrict__ out_b,
              float* __restrict__ out, int l) {
    extern __shared__ char sm[];
    float* P = (float*)sm;
    uint32_t smb = smem_u32(sm);

    int tid = threadIdx.x;
    int wi = tid >> 5;
    int lane = tid & 31;
    int q = lane >> 2, j = lane & 3;
    int b = blockIdx.y;
    int s0 = blockIdx.x * 64;
    int rows_valid = SS - s0;
    if (rows_valid > 64) rows_valid = 64;

    // params
    if (tid < 64) {
        P[P_ATTN + tid] = g_attn[b * DMODEL + tid];
        P[P_B1 + tid] = ff1_b[l * DMODEL + tid];
        P[P_B2 + tid] = ff2_b[l * DMODEL + tid];
        P[P_G1 + tid] = n1_g[l * DMODEL + tid];
        P[P_N1 + tid] = n1_b[l * DMODEL + tid];
        P[P_G2 + tid] = n2_g[l * DMODEL + tid];
        P[P_N2 + tid] = n2_b[l * DMODEL + tid];
        P[P_SUM + tid] = 0.0f;
    }
    P[P_OW + tid] = out_w[tid];
    if (tid < 2) P[P_OB + tid] = out_b[tid];

    // W tiles (split bf16, swizzled)
    const float* W1 = ff1_w + l * 4096;
    const float* W2 = ff2_w + l * 4096;
#pragma unroll
    for (int it = 0; it < 16; it++) {
        int i = tid + it * 128;
        int o = i >> 5, k2 = i & 31;
        uint32_t off = (uint32_t)(o * 128) + ((((uint32_t)(k2 >> 2)) ^ (o & 7u)) << 4) +
                       (k2 & 3) * 4;
        {
            float w0 = W1[o * 64 + k2 * 2], w1 = W1[o * 64 + k2 * 2 + 1];
            uint32_t hi = pack_hi(w0, w1);
            *(uint32_t*)(sm + SM_W1H + off) = hi;
            *(uint32_t*)(sm + SM_W1L + off) = pack_lo(w0, w1, hi);
        }
        {
            float w0 = W2[o * 64 + k2 * 2], w1 = W2[o * 64 + k2 * 2 + 1];
            uint32_t hi = pack_hi(w0, w1);
            *(uint32_t*)(sm + SM_W2H + off) = hi;
            *(uint32_t*)(sm + SM_W2L + off) = pack_lo(w0, w1, hi);
        }
    }

    // x load in frag layout + attn + LN1
    int r0 = wi * 16 + q, r1 = r0 + 8;
    bool v0ok = (r0 < rows_valid), v1ok = (r1 < rows_valid);
    float v0[16], v1[16];
    {
        const float* x0 = g_x + (size_t)(b * SS + s0 + r0) * 64;
        const float* x1 = g_x + (size_t)(b * SS + s0 + r1) * 64;
        float sm0 = 0.f, sq0 = 0.f, sm1 = 0.f, sq1 = 0.f;
#pragma unroll
        for (int nt = 0; nt < 8; nt++) {
            int c = nt * 8 + 2 * j;
            float2 a = P[P_ATTN + c] == P[P_ATTN + c]  // no-op guard keeps order
                           ? make_float2(P[P_ATTN + c], P[P_ATTN + c + 1])
                           : make_float2(0.f, 0.f);
            float2 t0 = v0ok ? *(const float2*)(x0 + c) : make_float2(0.f, 0.f);
            float2 t1 = v1ok ? *(const float2*)(x1 + c) : make_float2(0.f, 0.f);
            float a0 = t0.x + a.x, a1 = t0.y + a.y;
            float a2 = t1.x + a.x, a3 = t1.y + a.y;
            v0[2 * nt] = a0; v0[2 * nt + 1] = a1;
            v1[2 * nt] = a2; v1[2 * nt + 1] = a3;
            sm0 += a0 + a1; sq0 += a0 * a0 + a1 * a1;
            sm1 += a2 + a3; sq1 += a2 * a2 + a3 * a3;
        }
        sm0 += __shfl_xor_sync(0xffffffffu, sm0, 1);
        sq0 += __shfl_xor_sync(0xffffffffu, sq0, 1);
        sm1 += __shfl_xor_sync(0xffffffffu, sm1, 1);
        sq1 += __shfl_xor_sync(0xffffffffu, sq1, 1);
        sm0 += __shfl_xor_sync(0xffffffffu, sm0, 2);
        sq0 += __shfl_xor_sync(0xffffffffu, sq0, 2);
        sm1 += __shfl_xor_sync(0xffffffffu, sm1, 2);
        sq1 += __shfl_xor_sync(0xffffffffu, sq1, 2);
        float mu0 = sm0 * (1.0f / 64.0f);
        float rs0 = rsqrtf(sq0 * (1.0f / 64.0f) - mu0 * mu0 + EPS);
        float mu1 = sm1 * (1.0f / 64.0f);
        float rs1 = rsqrtf(sq1 * (1.0f / 64.0f) - mu1 * mu1 + EPS);
#pragma unroll
        for (int nt = 0; nt < 8; nt++) {
            int c = nt * 8 + 2 * j;
            float g0 = P[P_G1 + c], g1 = P[P_G1 + c + 1];
            float n0 = P[P_N1 + c], n1 = P[P_N1 + c + 1];
            float y0 = (v0[2 * nt] - mu0) * rs0 * g0 + n0;
            float y1 = (v0[2 * nt + 1] - mu0) * rs0 * g1 + n1;
            float y2 = (v1[2 * nt] - mu1) * rs1 * g0 + n0;
            float y3 = (v1[2 * nt + 1] - mu1) * rs1 * g1 + n1;
            uint32_t hi0 = pack_hi(y0, y1), hi1 = pack_hi(y2, y3);
            uint32_t o0 = tile_off((uint32_t)r0, (uint32_t)nt) + 4 * j;
            uint32_t o1 = tile_off((uint32_t)r1, (uint32_t)nt) + 4 * j;
            *(uint32_t*)(sm + SM_AH + o0) = hi0;
            *(uint32_t*)(sm + SM_AL + o0) = pack_lo(y0, y1, hi0);
            *(uint32_t*)(sm + SM_AH + o1) = hi1;
            *(uint32_t*)(sm + SM_AL + o1) = pack_lo(y2, y3, hi1);
        }
    }
    __syncthreads();

    // GEMM1
    float d1[8][4];
#pragma unroll
    for (int n = 0; n < 8; n++)
#pragma unroll
        for (int k = 0; k < 4; k++) d1[n][k] = 0.f;
    gemm64(d1, smb + SM_AH, smb + SM_AL, smb + SM_W1H, smb + SM_W1L, wi, lane);
    __syncthreads();  // W1 tiles now dead -> reuse as H tiles

    // relu -> H tiles (overwrite W1H/W1L)
#pragma unroll
    for (int nt = 0; nt < 8; nt++) {
        int c = nt * 8 + 2 * j;
        float b1a = P[P_B1 + c], b1b = P[P_B1 + c + 1];
        float h0 = fmaxf(d1[nt][0] + b1a, 0.f);
        float h1 = fmaxf(d1[nt][1] + b1b, 0.f);
        float h2 = fmaxf(d1[nt][2] + b1a, 0.f);
        float h3 = fmaxf(d1[nt][3] + b1b, 0.f);
        uint32_t hi0 = pack_hi(h0, h1), hi1 = pack_hi(h2, h3);
        uint32_t o0 = tile_off((uint32_t)r0, (uint32_t)nt) + 4 * j;
        uint32_t o1 = tile_off((uint32_t)r1, (uint32_t)nt) + 4 * j;
        *(uint32_t*)(sm + SM_W1H + o0) = hi0;
        *(uint32_t*)(sm + SM_W1L + o0) = pack_lo(h0, h1, hi0);
        *(uint32_t*)(sm + SM_W1H + o1) = hi1;
        *(uint32_t*)(sm + SM_W1L + o1) = pack_lo(h2, h3, hi1);
    }
    __syncthreads();

    // GEMM2 (A = H tiles)
    float d2[8][4];
#pragma unroll
    for (int n = 0; n < 8; n++)
#pragma unroll
        for (int k = 0; k < 4; k++) d2[n][k] = 0.f;
    gemm64(d2, smb + SM_W1H, smb + SM_W1L, smb + SM_W2H, smb + SM_W2L, wi, lane);

    // residual (reload y from Ah/Al) + bias + LN2
    {
        float sm0 = 0.f, sq0 = 0.f, sm1 = 0.f, sq1 = 0.f;
#pragma unroll
        for (int nt = 0; nt < 8; nt++) {
            int c = nt * 8 + 2 * j;
            uint32_t o0 = tile_off((uint32_t)r0, (uint32_t)nt) + 4 * j;
            uint32_t o1 = tile_off((uint32_t)r1, (uint32_t)nt) + 4 * j;
            uint32_t yh0 = *(const uint32_t*)(sm + SM_AH + o0);
            uint32_t yl0 = *(const uint32_t*)(sm + SM_AL + o0);
            uint32_t yh1 = *(const uint32_t*)(sm + SM_AH + o1);
            uint32_t yl1 = *(const uint32_t*)(sm + SM_AL + o1);
            float b2a = P[P_B2 + c], b2b = P[P_B2 + c + 1];
            float a0 = d2[nt][0] + b2a + unpack_add(yh0, yl0, 0);
            float a1 = d2[nt][1] + b2b + unpack_add(yh0, yl0, 1);
            float a2 = d2[nt][2] + b2a + unpack_add(yh1, yl1, 0);
            float a3 = d2[nt][3] + b2b + unpack_add(yh1, yl1, 1);
            v0[2 * nt] = a0; v0[2 * nt + 1] = a1;
            v1[2 * nt] = a2; v1[2 * nt + 1] = a3;
            sm0 += a0 + a1; sq0 += a0 * a0 + a1 * a1;
            sm1 += a2 + a3; sq1 += a2 * a2 + a3 * a3;
        }
        sm0 += __shfl_xor_sync(0xffffffffu, sm0, 1);
        sq0 += __shfl_xor_sync(0xffffffffu, sq0, 1);
        sm1 += __shfl_xor_sync(0xffffffffu, sm1, 1);
        sq1 += __shfl_xor_sync(0xffffffffu, sq1, 1);
        sm0 += __shfl_xor_sync(0xffffffffu, sm0, 2);
        sq0 += __shfl_xor_sync(0xffffffffu, sq0, 2);
        sm1 += __shfl_xor_sync(0xffffffffu, sm1, 2);
        sq1 += __shfl_xor_sync(0xffffffffu, sq1, 2);
        float mu0 = sm0 * (1.0f / 64.0f);
        float rs0 = rsqrtf(sq0 * (1.0f / 64.0f) - mu0 * mu0 + EPS);
        float mu1 = sm1 * (1.0f / 64.0f);
        float rs1 = rsqrtf(sq1 * (1.0f / 64.0f) - mu1 * mu1 + EPS);
#pragma unroll
        for (int nt = 0; nt < 8; nt++) {
            int c = nt * 8 + 2 * j;
            float g0 = P[P_G2 + c], g1 = P[P_G2 + c + 1];
            float n0 = P[P_N2 + c], n1 = P[P_N2 + c + 1];
            v0[2 * nt] = (v0[2 * nt] - mu0) * rs0 * g0 + n0;
            v0[2 * nt + 1] = (v0[2 * nt + 1] - mu0) * rs0 * g1 + n1;
            v1[2 * nt] = (v1[2 * nt] - mu1) * rs1 * g0 + n0;
            v1[2 * nt + 1] = (v1[2 * nt + 1] - mu1) * rs1 * g1 + n1;
        }
    }

    if (l < NLAYERS - 1) {
        float* x0 = g_x + (size_t)(b * SS + s0 + r0) * 64;
        float* x1 = g_x + (size_t)(b * SS + s0 + r1) * 64;
#pragma unroll
        for (int nt = 0; nt < 8; nt++) {
            int c = nt * 8 + 2 * j;
            if (v0ok) *(float2*)(x0 + c) = make_float2(v0[2 * nt], v0[2 * nt + 1]);
            if (v1ok) *(float2*)(x1 + c) = make_float2(v1[2 * nt], v1[2 * nt + 1]);
        }
        // column sums (exclude invalid rows)
        float s[16];
#pragma unroll
        for (int i = 0; i < 16; i++)
            s[i] = (v0ok ? v0[i] : 0.f) + (v1ok ? v1[i] : 0.f);
#pragma unroll
        for (int i = 0; i < 16; i++) {
            s[i] += __shfl_xor_sync(0xffffffffu, s[i], 4);
            s[i] += __shfl_xor_sync(0xffffffffu, s[i], 8);
            s[i] += __shfl_xor_sync(0xffffffffu, s[i], 16);
        }
        if (q == 0) {
#pragma unroll
            for (int nt = 0; nt < 8; nt++) {
                int c = nt * 8 + 2 * j;
                atomicAdd(&P[P_SUM + c], s[2 * nt]);
                atomicAdd(&P[P_SUM + c + 1], s[2 * nt + 1]);
            }
        }
        __syncthreads();
        if (tid < 64)
            atomicAdd(&g_sums[(l + 1) * BB * DMODEL + b * DMODEL + tid],
                      P[P_SUM + tid]);
    } else {
        float p00 = 0.f, p10 = 0.f, p01 = 0.f, p11 = 0.f;
#pragma unroll
        for (int nt = 0; nt < 8; nt++) {
            int c = nt * 8 + 2 * j;
            float w0 = P[P_OW + c], w1 = P[P_OW + c + 1];
            float u0 = P[P_OW + 64 + c], u1 = P[P_OW + 64 + c + 1];
            p00 = fmaf(v0[2 * nt], w0, fmaf(v0[2 * nt + 1], w1, p00));
            p10 = fmaf(v0[2 * nt], u0, fmaf(v0[2 * nt + 1], u1, p10));
            p01 = fmaf(v1[2 * nt], w0, fmaf(v1[2 * nt + 1], w1, p01));
            p11 = fmaf(v1[2 * nt], u0, fmaf(v1[2 * nt + 1], u1, p11));
        }
        p00 += __shfl_xor_sync(0xffffffffu, p00, 1);
        p10 += __shfl_xor_sync(0xffffffffu, p10, 1);
        p01 += __shfl_xor_sync(0xffffffffu, p01, 1);
        p11 += __shfl_xor_sync(0xffffffffu, p11, 1);
        p00 += __shfl_xor_sync(0xffffffffu, p00, 2);
        p10 += __shfl_xor_sync(0xffffffffu, p10, 2);
        p01 += __shfl_xor_sync(0xffffffffu, p01, 2);
        p11 += __shfl_xor_sync(0xffffffffu, p11, 2);
        if (j == 0) {
            if (v0ok)
                *(float2*)(out + (size_t)(b * SS + s0 + r0) * 2) =
                    make_float2(p00 + P[P_OB], p10 + P[P_OB + 1]);
            if (v1ok)
                *(float2*)(out + (size_t)(b * SS + s0 + r1) * 2) =
                    make_float2(p01 + P[P_OB], p11 + P[P_OB + 1]);
        }
    }
}

// ---------------------------------------------------------------------------
extern "C" void kernel_launch(void* const* d_in, const int* in_sizes, int n_in,
                              void* d_out, int out_size) {
    const int*   tokens = (const int*)d_in[0];
    const float* emb    = (const float*)d_in[1];
    const float* lin_w  = (const float*)d_in[2];
    const float* lin_b  = (const float*)d_in[3];
    const float* ff1_w  = (const float*)d_in[4];
    const float* ff1_b  = (const float*)d_in[5];
    const float* ff2_w  = (const float*)d_in[6];
    const float* ff2_b  = (const float*)d_in[7];
    const float* n1g    = (const float*)d_in[8];
    const float* n1b    = (const float*)d_in[9];
    const float* n2g    = (const float*)d_in[10];
    const float* n2b    = (const float*)d_in[11];
    const float* ow     = (const float*)d_in[12];
    const float* ob     = (const float*)d_in[13];
    float* out = (float*)d_out;

    cudaFuncSetAttribute(k_layer4, cudaFuncAttributeMaxDynamicSharedMemorySize,
                         SM_TOTAL);

    k_init<<<128, 256>>>();
    k_embed<<<dim3(8, BB), 256>>>(tokens, emb);
    for (int l = 0; l < NLAYERS; l++) {
        k_attn<<<BB, 64>>>(lin_w, lin_b, l);
        k_layer4<<<dim3(16, BB), 128, SM_TOTAL>>>(ff1_w, ff1_b, ff2_w, ff2_b,
                                                  n1g, n1b, n2g, n2b, ow, ob,
                                                  out, l);
    }
}